// round 8
// baseline (speedup 1.0000x reference)
#include <cuda_runtime.h>
#include <cuda_bf16.h>
#include <cstdint>

#define BB 4
#define SS 2048
#define EE 1024
#define HH 16
#define DD 64
#define NTILES 32
#define QROWS 64             // q-rows per CTA (4 warps x 16)
#define PK 68                // Kt pitch: QK B-frag loads conflict-free
#define PVP 72               // Vs pitch: PV B-frag loads conflict-free

static const long long OUT_ELEMS  = (long long)BB * SS * EE;        // 8388608
static const long long ATTN_ELEMS = (long long)BB * HH * SS * SS;   // 268435456

#define FULLM 0xFFFFFFFFu

// per-row normalization constant: log2(1 / sum_k exp(q.k/32))
__device__ float g_logc[BB * HH * SS];

__device__ __forceinline__ uint32_t f2tf(float x) {
    uint32_t r;
    asm("cvt.rna.tf32.f32 %0, %1;" : "=r"(r) : "f"(x));
    return r;
}

__device__ __forceinline__ void mma_tf32(float& c0, float& c1, float& c2, float& c3,
                                         uint32_t a0, uint32_t a1, uint32_t a2, uint32_t a3,
                                         uint32_t b0, uint32_t b1)
{
    asm volatile(
        "mma.sync.aligned.m16n8k8.row.col.f32.tf32.tf32.f32 "
        "{%0,%1,%2,%3}, {%4,%5,%6,%7}, {%8,%9}, {%0,%1,%2,%3};"
        : "+f"(c0), "+f"(c1), "+f"(c2), "+f"(c3)
        : "r"(a0), "r"(a1), "r"(a2), "r"(a3), "r"(b0), "r"(b1));
}

// m16 A fragments: 8 k-blocks x 4 regs = 32 regs
#define LOAD_A16(A, qg, qr0)                                                 \
    _Pragma("unroll")                                                        \
    for (int kb = 0; kb < 8; kb++) {                                         \
        A[kb][0] = f2tf(qg[(size_t)(qr0)       * EE + kb * 8 + tid4]);       \
        A[kb][1] = f2tf(qg[(size_t)((qr0) + 8) * EE + kb * 8 + tid4]);       \
        A[kb][2] = f2tf(qg[(size_t)(qr0)       * EE + kb * 8 + tid4 + 4]);   \
        A[kb][3] = f2tf(qg[(size_t)((qr0) + 8) * EE + kb * 8 + tid4 + 4]);   \
    }

extern __shared__ float smem_dyn[];

// ============ Kernel 1: row sums (QK + exp + reduce only) ============
__global__ __launch_bounds__(128, 6)
void attn_sums(const float* __restrict__ q, const float* __restrict__ k)
{
    float* Kt = smem_dyn;              // [64 keys][PK] tf32-rounded

    const int b = blockIdx.z, h = blockIdx.y, qt = blockIdx.x;
    const int t = threadIdx.x, w = t >> 5, lane = t & 31;
    const int gid = lane >> 2, tid4 = lane & 3;
    const float cs = 1.4426950408889634f / 32.0f;   // log2(e)/32
    const int qr0 = w * 16 + gid;

    const float* qg = q + ((size_t)(b * SS + qt * QROWS)) * EE + h * DD;
    uint32_t A[8][4];
    LOAD_A16(A, qg, qr0)

    const float* kg0 = k + ((size_t)b * SS) * EE + h * DD;
    float lp0 = 0.f, lp1 = 0.f;

    for (int kt = 0; kt < NTILES; kt++) {
        const float* kg = kg0 + (size_t)kt * 64 * EE;
        for (int i = t; i < 1024; i += 128) {
            int r = i >> 4, c4 = i & 15;
            float4 kv = *(const float4*)(kg + (size_t)r * EE + c4 * 4);
            float4 ko;
            ko.x = __uint_as_float(f2tf(kv.x));
            ko.y = __uint_as_float(f2tf(kv.y));
            ko.z = __uint_as_float(f2tf(kv.z));
            ko.w = __uint_as_float(f2tf(kv.w));
            *(float4*)&Kt[r * PK + c4 * 4] = ko;
        }
        __syncthreads();

#pragma unroll
        for (int nb = 0; nb < 8; nb++) {
            float S[4] = {0.f, 0.f, 0.f, 0.f};
#pragma unroll
            for (int kb = 0; kb < 8; kb++) {
                uint32_t b0 = __float_as_uint(Kt[(nb * 8 + gid) * PK + kb * 8 + tid4]);
                uint32_t b1 = __float_as_uint(Kt[(nb * 8 + gid) * PK + kb * 8 + tid4 + 4]);
                mma_tf32(S[0], S[1], S[2], S[3],
                         A[kb][0], A[kb][1], A[kb][2], A[kb][3], b0, b1);
            }
            lp0 += exp2f(S[0] * cs) + exp2f(S[1] * cs);
            lp1 += exp2f(S[2] * cs) + exp2f(S[3] * cs);
        }
        __syncthreads();
    }

    lp0 += __shfl_xor_sync(FULLM, lp0, 1);
    lp0 += __shfl_xor_sync(FULLM, lp0, 2);
    lp1 += __shfl_xor_sync(FULLM, lp1, 1);
    lp1 += __shfl_xor_sync(FULLM, lp1, 2);
    if (tid4 == 0) {
        size_t base = (size_t)((b * HH + h) * SS) + (size_t)qt * QROWS;
        g_logc[base + qr0]     = -log2f(lp0);
        g_logc[base + qr0 + 8] = -log2f(lp1);
    }
}

// ============ Kernel 2: normalized attn + O, P register-resident ============
// Per 8-key chunk: S (mma) -> P=exp2(S*cs+logc) -> STG attn (from regs) ->
// shuffle C-frag -> A-frag -> PV accumulate. No Ps smem at all.
__global__ __launch_bounds__(128, 5)
void attn_main(const float* __restrict__ q, const float* __restrict__ k,
               const float* __restrict__ v, float* __restrict__ out,
               float* __restrict__ attn, int write_attn)
{
    float* Kt = smem_dyn;              // [64 keys][PK]
    float* Vs = Kt + 64 * PK;          // [64 keys][PVP]

    const int b = blockIdx.z, h = blockIdx.y, qt = blockIdx.x;
    const int t = threadIdx.x, w = t >> 5, lane = t & 31;
    const int gid = lane >> 2, tid4 = lane & 3;
    const float cs = 1.4426950408889634f / 32.0f;
    const int qr0 = w * 16 + gid;

    // shuffle sources for C->A fragment permutation (within each 4-lane quad)
    const int srcA = (lane & ~3) | (tid4 >> 1);      // cols tid4   (0..3)
    const int srcB = srcA + 2;                       // cols tid4+4 (4..7)
    const bool odd = (tid4 & 1) != 0;

    const float* qg = q + ((size_t)(b * SS + qt * QROWS)) * EE + h * DD;
    uint32_t A[8][4];
    LOAD_A16(A, qg, qr0)

    float c0add, c1add;
    {
        size_t base = (size_t)((b * HH + h) * SS) + (size_t)qt * QROWS;
        c0add = g_logc[base + qr0];
        c1add = g_logc[base + qr0 + 8];
    }

    float Oacc[8][4];
#pragma unroll
    for (int nb = 0; nb < 8; nb++)
#pragma unroll
        for (int j = 0; j < 4; j++) Oacc[nb][j] = 0.f;

    const float* kg0 = k + ((size_t)b * SS) * EE + h * DD;
    const float* vg0 = v + ((size_t)b * SS) * EE + h * DD;
    float* attng = attn + ((size_t)((b * HH + h) * SS) + (size_t)qt * QROWS) * SS;

    for (int kt = 0; kt < NTILES; kt++) {
        const float* kg = kg0 + (size_t)kt * 64 * EE;
        const float* vg = vg0 + (size_t)kt * 64 * EE;
        for (int i = t; i < 1024; i += 128) {
            int r = i >> 4, c4 = i & 15;
            float4 kv = *(const float4*)(kg + (size_t)r * EE + c4 * 4);
            float4 ko;
            ko.x = __uint_as_float(f2tf(kv.x));
            ko.y = __uint_as_float(f2tf(kv.y));
            ko.z = __uint_as_float(f2tf(kv.z));
            ko.w = __uint_as_float(f2tf(kv.w));
            *(float4*)&Kt[r * PK + c4 * 4] = ko;
            float4 vv = *(const float4*)(vg + (size_t)r * EE + c4 * 4);
            float4 vo;
            vo.x = __uint_as_float(f2tf(vv.x));
            vo.y = __uint_as_float(f2tf(vv.y));
            vo.z = __uint_as_float(f2tf(vv.z));
            vo.w = __uint_as_float(f2tf(vv.w));
            *(float4*)&Vs[r * PVP + c4 * 4] = vo;
        }
        __syncthreads();

#pragma unroll
        for (int nb = 0; nb < 8; nb++) {
            // ---- S = Q K^T for this 8-key chunk ----
            float S[4] = {0.f, 0.f, 0.f, 0.f};
#pragma unroll
            for (int kb = 0; kb < 8; kb++) {
                uint32_t b0 = __float_as_uint(Kt[(nb * 8 + gid) * PK + kb * 8 + tid4]);
                uint32_t b1 = __float_as_uint(Kt[(nb * 8 + gid) * PK + kb * 8 + tid4 + 4]);
                mma_tf32(S[0], S[1], S[2], S[3],
                         A[kb][0], A[kb][1], A[kb][2], A[kb][3], b0, b1);
            }

            // ---- normalized P (C-frag layout: rows qr0/qr0+8, cols nb*8+2*tid4,+1) ----
            float p0 = exp2f(fmaf(S[0], cs, c0add));
            float p1 = exp2f(fmaf(S[1], cs, c0add));
            float p2 = exp2f(fmaf(S[2], cs, c1add));
            float p3 = exp2f(fmaf(S[3], cs, c1add));

            // ---- attn store straight from registers (32B sector per lane-quad) ----
            if (write_attn) {
                float* ag = attng + kt * 64 + nb * 8 + 2 * tid4;
                *(float2*)(ag + (size_t)qr0       * SS) = make_float2(p0, p1);
                *(float2*)(ag + (size_t)(qr0 + 8) * SS) = make_float2(p2, p3);
            }

            // ---- C-frag -> A-frag permutation via shuffles ----
            float s0 = __shfl_sync(FULLM, p0, srcA);
            float s1 = __shfl_sync(FULLM, p1, srcA);
            float s2 = __shfl_sync(FULLM, p2, srcA);
            float s3 = __shfl_sync(FULLM, p3, srcA);
            uint32_t pa0 = f2tf(odd ? s1 : s0);      // P[gid,   nb*8+tid4]
            uint32_t pa1 = f2tf(odd ? s3 : s2);      // P[gid+8, nb*8+tid4]
            s0 = __shfl_sync(FULLM, p0, srcB);
            s1 = __shfl_sync(FULLM, p1, srcB);
            s2 = __shfl_sync(FULLM, p2, srcB);
            s3 = __shfl_sync(FULLM, p3, srcB);
            uint32_t pa2 = f2tf(odd ? s1 : s0);      // P[gid,   nb*8+tid4+4]
            uint32_t pa3 = f2tf(odd ? s3 : s2);      // P[gid+8, nb*8+tid4+4]

            // ---- O += P_chunk @ V[nb*8 .. nb*8+8, :] ----
            const int kbase = nb * 8;
#pragma unroll
            for (int nbp = 0; nbp < 8; nbp++) {
                uint32_t b0 = __float_as_uint(Vs[(kbase + tid4)     * PVP + nbp * 8 + gid]);
                uint32_t b1 = __float_as_uint(Vs[(kbase + tid4 + 4) * PVP + nbp * 8 + gid]);
                mma_tf32(Oacc[nbp][0], Oacc[nbp][1], Oacc[nbp][2], Oacc[nbp][3],
                         pa0, pa1, pa2, pa3, b0, b1);
            }
        }
        __syncthreads();   // protect Kt/Vs restage
    }

    // ---- out = O (already normalized) ----
    float* og = out + ((size_t)(b * SS + qt * QROWS)) * EE + h * DD;
#pragma unroll
    for (int nb = 0; nb < 8; nb++) {
        *(float2*)(og + (size_t)qr0       * EE + nb * 8 + 2 * tid4) =
            make_float2(Oacc[nb][0], Oacc[nb][1]);
        *(float2*)(og + (size_t)(qr0 + 8) * EE + nb * 8 + 2 * tid4) =
            make_float2(Oacc[nb][2], Oacc[nb][3]);
    }
}

static const size_t SHMEM_SUMS = (size_t)64 * PK * sizeof(float);              // 17408
static const size_t SHMEM_MAIN = (size_t)64 * (PK + PVP) * sizeof(float);      // 35840

static bool setup_once()
{
    cudaFuncSetAttribute(attn_sums, cudaFuncAttributeMaxDynamicSharedMemorySize,
                         (int)SHMEM_SUMS);
    cudaFuncSetAttribute(attn_main, cudaFuncAttributeMaxDynamicSharedMemorySize,
                         (int)SHMEM_MAIN);
    return true;
}

extern "C" void kernel_launch(void* const* d_in, const int* in_sizes, int n_in,
                              void* d_out, int out_size)
{
    static bool ready = setup_once();
    (void)ready;

    const float* q = (const float*)d_in[0];
    const float* k = (const float*)d_in[1];
    const float* v = (const float*)d_in[2];
    float* out  = (float*)d_out;
    float* attn = out + OUT_ELEMS;

    const long long need = OUT_ELEMS + ATTN_ELEMS;
    const int write_attn = ((long long)out_size >= need) ? 1 : 0;

    dim3 grid(SS / QROWS, HH, BB);
    attn_sums<<<grid, 128, SHMEM_SUMS>>>(q, k);
    attn_main<<<grid, 128, SHMEM_MAIN>>>(q, k, v, out, attn, write_attn);
}

// round 13
// speedup vs baseline: 1.4655x; 1.4655x over previous
#include <cuda_runtime.h>
#include <cuda_fp16.h>
#include <cstdint>

#define BB 4
#define SS 2048
#define EE 1024
#define HH 16
#define DD 64
#define NTILES 32
#define QROWS 64             // q-rows per CTA (4 warps x 16)
#define PKH 72               // Kt pitch in halfs (144B rows): QK B-frag conflict-free
#define PVP 72               // Vs pitch (floats): PV B-frag loads conflict-free
#define PP 68                // Ps pitch (floats): PV A-frag loads conflict-free

static const long long OUT_ELEMS  = (long long)BB * SS * EE;        // 8388608
static const long long ATTN_ELEMS = (long long)BB * HH * SS * SS;   // 268435456

#define FULLM 0xFFFFFFFFu

// per-row normalization constant: log2(1 / sum_k exp(q.k/32))
__device__ float g_logc[BB * HH * SS];

__device__ __forceinline__ uint32_t f2tf(float x) {
    uint32_t r;
    asm("cvt.rna.tf32.f32 %0, %1;" : "=r"(r) : "f"(x));
    return r;
}

__device__ __forceinline__ uint32_t packh2(float x, float y) {
    __half2 h = __floats2half2_rn(x, y);
    uint32_t r;
    memcpy(&r, &h, 4);
    return r;
}

// fp16 mma m16n8k16, fp32 accumulate
__device__ __forceinline__ void mma_f16(float& c0, float& c1, float& c2, float& c3,
                                        uint32_t a0, uint32_t a1, uint32_t a2, uint32_t a3,
                                        uint32_t b0, uint32_t b1)
{
    asm volatile(
        "mma.sync.aligned.m16n8k16.row.col.f32.f16.f16.f32 "
        "{%0,%1,%2,%3}, {%4,%5,%6,%7}, {%8,%9}, {%0,%1,%2,%3};"
        : "+f"(c0), "+f"(c1), "+f"(c2), "+f"(c3)
        : "r"(a0), "r"(a1), "r"(a2), "r"(a3), "r"(b0), "r"(b1));
}

// tf32 mma m16n8k8 (PV path, unchanged from round 7)
__device__ __forceinline__ void mma_tf32(float& c0, float& c1, float& c2, float& c3,
                                         uint32_t a0, uint32_t a1, uint32_t a2, uint32_t a3,
                                         uint32_t b0, uint32_t b1)
{
    asm volatile(
        "mma.sync.aligned.m16n8k8.row.col.f32.tf32.tf32.f32 "
        "{%0,%1,%2,%3}, {%4,%5,%6,%7}, {%8,%9}, {%0,%1,%2,%3};"
        : "+f"(c0), "+f"(c1), "+f"(c2), "+f"(c3)
        : "r"(a0), "r"(a1), "r"(a2), "r"(a3), "r"(b0), "r"(b1));
}

// fp16 A fragments for m16n8k16: 4 k-blocks x 4 half2 regs = 16 regs
// a0={Q[r,2t4],Q[r,2t4+1]} a1=rows+8  a2=cols+8  a3=rows+8,cols+8
#define LOAD_A16H(A, qg, qr0)                                                     \
    _Pragma("unroll")                                                             \
    for (int kb = 0; kb < 4; kb++) {                                              \
        const float* q0 = qg + (size_t)(qr0)       * EE + kb * 16 + 2 * tid4;     \
        const float* q1 = qg + (size_t)((qr0) + 8) * EE + kb * 16 + 2 * tid4;     \
        A[kb][0] = packh2(q0[0], q0[1]);                                          \
        A[kb][1] = packh2(q1[0], q1[1]);                                          \
        A[kb][2] = packh2(q0[8], q0[9]);                                          \
        A[kb][3] = packh2(q1[8], q1[9]);                                          \
    }

// stage one K row-chunk: float4 (4 dims of key r) -> 4 halfs -> one 8B store
#define STAGE_K_ITER(Kt, kg, r, c4)                                               \
    {                                                                             \
        float4 kv = *(const float4*)((kg) + (size_t)(r) * EE + (c4) * 4);         \
        uint2 hk;                                                                 \
        hk.x = packh2(kv.x, kv.y);                                                \
        hk.y = packh2(kv.z, kv.w);                                                \
        *(uint2*)&(Kt)[(r) * PKH + (c4) * 4] = hk;                                \
    }

extern __shared__ float smem_dyn[];

// ============ Kernel 1: row sums (fp16 QK + exp + reduce only) ============
__global__ __launch_bounds__(128, 6)
void attn_sums(const float* __restrict__ q, const float* __restrict__ k)
{
    __half* Kt = (__half*)smem_dyn;    // [64 keys][PKH halfs]

    const int b = blockIdx.z, h = blockIdx.y, qt = blockIdx.x;
    const int t = threadIdx.x, w = t >> 5, lane = t & 31;
    const int gid = lane >> 2, tid4 = lane & 3;
    const float cs = 1.4426950408889634f / 32.0f;   // log2(e)/32
    const int qr0 = w * 16 + gid;

    const float* qg = q + ((size_t)(b * SS + qt * QROWS)) * EE + h * DD;
    uint32_t A[4][4];
    LOAD_A16H(A, qg, qr0)

    const float* kg0 = k + ((size_t)b * SS) * EE + h * DD;
    float lp0 = 0.f, lp1 = 0.f;

    for (int kt = 0; kt < NTILES; kt++) {
        const float* kg = kg0 + (size_t)kt * 64 * EE;
        for (int i = t; i < 1024; i += 128) {
            int r = i >> 4, c4 = i & 15;
            STAGE_K_ITER(Kt, kg, r, c4)
        }
        __syncthreads();

#pragma unroll
        for (int nb = 0; nb < 8; nb++) {
            float S[4] = {0.f, 0.f, 0.f, 0.f};
#pragma unroll
            for (int kb = 0; kb < 4; kb++) {
                uint32_t b0 = *(const uint32_t*)&Kt[(nb * 8 + gid) * PKH + kb * 16 + 2 * tid4];
                uint32_t b1 = *(const uint32_t*)&Kt[(nb * 8 + gid) * PKH + kb * 16 + 2 * tid4 + 8];
                mma_f16(S[0], S[1], S[2], S[3],
                        A[kb][0], A[kb][1], A[kb][2], A[kb][3], b0, b1);
            }
            lp0 += exp2f(S[0] * cs) + exp2f(S[1] * cs);
            lp1 += exp2f(S[2] * cs) + exp2f(S[3] * cs);
        }
        __syncthreads();
    }

    lp0 += __shfl_xor_sync(FULLM, lp0, 1);
    lp0 += __shfl_xor_sync(FULLM, lp0, 2);
    lp1 += __shfl_xor_sync(FULLM, lp1, 1);
    lp1 += __shfl_xor_sync(FULLM, lp1, 2);
    if (tid4 == 0) {
        size_t base = (size_t)((b * HH + h) * SS) + (size_t)qt * QROWS;
        g_logc[base + qr0]     = -log2f(lp0);
        g_logc[base + qr0 + 8] = -log2f(lp1);
    }
}

// ============ Kernel 2: normalized attn + O ============
// fp16 QK -> fp32 P in smem -> tf32 PV (round-7 structure otherwise)
__global__ __launch_bounds__(128, 5)
void attn_main(const float* __restrict__ q, const float* __restrict__ k,
               const float* __restrict__ v, float* __restrict__ out,
               float* __restrict__ attn, int write_attn)
{
    __half* Kt = (__half*)smem_dyn;                 // [64 keys][PKH halfs]  9216 B
    float*  Vs = smem_dyn + (64 * PKH) / 2;         // [64 keys][PVP floats] 18432 B
    float*  Ps = Vs + 64 * PVP;                     // [64 q][PP floats]     17408 B

    const int b = blockIdx.z, h = blockIdx.y, qt = blockIdx.x;
    const int t = threadIdx.x, w = t >> 5, lane = t & 31;
    const int gid = lane >> 2, tid4 = lane & 3;
    const float cs = 1.4426950408889634f / 32.0f;
    const int qr0 = w * 16 + gid;

    const float* qg = q + ((size_t)(b * SS + qt * QROWS)) * EE + h * DD;
    uint32_t A[4][4];
    LOAD_A16H(A, qg, qr0)

    float c0add, c1add;
    {
        size_t base = (size_t)((b * HH + h) * SS) + (size_t)qt * QROWS;
        c0add = g_logc[base + qr0];
        c1add = g_logc[base + qr0 + 8];
    }

    float Oacc[8][4];
#pragma unroll
    for (int nb = 0; nb < 8; nb++)
#pragma unroll
        for (int j = 0; j < 4; j++) Oacc[nb][j] = 0.f;

    const float* kg0 = k + ((size_t)b * SS) * EE + h * DD;
    const float* vg0 = v + ((size_t)b * SS) * EE + h * DD;
    float* attng = attn + ((size_t)((b * HH + h) * SS) + (size_t)qt * QROWS) * SS;

    for (int kt = 0; kt < NTILES; kt++) {
        const float* kg = kg0 + (size_t)kt * 64 * EE;
        const float* vg = vg0 + (size_t)kt * 64 * EE;
        for (int i = t; i < 1024; i += 128) {
            int r = i >> 4, c4 = i & 15;
            STAGE_K_ITER(Kt, kg, r, c4)
            float4 vv = *(const float4*)(vg + (size_t)r * EE + c4 * 4);
            float4 vo;
            vo.x = __uint_as_float(f2tf(vv.x));
            vo.y = __uint_as_float(f2tf(vv.y));
            vo.z = __uint_as_float(f2tf(vv.z));
            vo.w = __uint_as_float(f2tf(vv.w));
            *(float4*)&Vs[r * PVP + c4 * 4] = vo;
        }
        __syncthreads();

        // ---- QK (fp16, nb-outer) + normalized exp -> Ps ----
#pragma unroll
        for (int nb = 0; nb < 8; nb++) {
            float S[4] = {0.f, 0.f, 0.f, 0.f};
#pragma unroll
            for (int kb = 0; kb < 4; kb++) {
                uint32_t b0 = *(const uint32_t*)&Kt[(nb * 8 + gid) * PKH + kb * 16 + 2 * tid4];
                uint32_t b1 = *(const uint32_t*)&Kt[(nb * 8 + gid) * PKH + kb * 16 + 2 * tid4 + 8];
                mma_f16(S[0], S[1], S[2], S[3],
                        A[kb][0], A[kb][1], A[kb][2], A[kb][3], b0, b1);
            }
            float p0 = exp2f(fmaf(S[0], cs, c0add));
            float p1 = exp2f(fmaf(S[1], cs, c0add));
            float p2 = exp2f(fmaf(S[2], cs, c1add));
            float p3 = exp2f(fmaf(S[3], cs, c1add));
            *(float2*)&Ps[(size_t)qr0       * PP + nb * 8 + 2 * tid4] = make_float2(p0, p1);
            *(float2*)&Ps[(size_t)(qr0 + 8) * PP + nb * 8 + 2 * tid4] = make_float2(p2, p3);
        }
        // warp-private Ps rows: no barrier needed before PV / attn store.

        // ---- O += P V (tf32, unchanged) ----
#pragma unroll
        for (int kb = 0; kb < 8; kb++) {
            uint32_t pa0 = f2tf(Ps[(size_t)qr0       * PP + kb * 8 + tid4]);
            uint32_t pa1 = f2tf(Ps[(size_t)(qr0 + 8) * PP + kb * 8 + tid4]);
            uint32_t pa2 = f2tf(Ps[(size_t)qr0       * PP + kb * 8 + tid4 + 4]);
            uint32_t pa3 = f2tf(Ps[(size_t)(qr0 + 8) * PP + kb * 8 + tid4 + 4]);
#pragma unroll
            for (int nb = 0; nb < 8; nb++) {
                uint32_t b0 = __float_as_uint(Vs[(kb * 8 + tid4)     * PVP + nb * 8 + gid]);
                uint32_t b1 = __float_as_uint(Vs[(kb * 8 + tid4 + 4) * PVP + nb * 8 + gid]);
                mma_tf32(Oacc[nb][0], Oacc[nb][1], Oacc[nb][2], Oacc[nb][3],
                         pa0, pa1, pa2, pa3, b0, b1);
            }
        }

        // ---- store normalized P tile (each warp its own 16 rows) ----
        if (write_attn) {
            float* ag = attng + kt * 64;
            for (int i = lane; i < 256; i += 32) {
                int r = w * 16 + (i >> 4), c4 = i & 15;
                *(float4*)(ag + (size_t)r * SS + c4 * 4) = *(const float4*)&Ps[r * PP + c4 * 4];
            }
        }
        __syncthreads();   // protect Kt/Vs restage
    }

    // ---- out = O (already normalized) ----
    float* og = out + ((size_t)(b * SS + qt * QROWS)) * EE + h * DD;
#pragma unroll
    for (int nb = 0; nb < 8; nb++) {
        *(float2*)(og + (size_t)qr0       * EE + nb * 8 + 2 * tid4) =
            make_float2(Oacc[nb][0], Oacc[nb][1]);
        *(float2*)(og + (size_t)(qr0 + 8) * EE + nb * 8 + 2 * tid4) =
            make_float2(Oacc[nb][2], Oacc[nb][3]);
    }
}

static const size_t SHMEM_SUMS = (size_t)64 * PKH * sizeof(__half);                         // 9216
static const size_t SHMEM_MAIN = (size_t)64 * PKH * sizeof(__half)
                               + (size_t)64 * (PVP + PP) * sizeof(float);                   // 45056

static bool setup_once()
{
    cudaFuncSetAttribute(attn_sums, cudaFuncAttributeMaxDynamicSharedMemorySize,
                         (int)SHMEM_SUMS);
    cudaFuncSetAttribute(attn_main, cudaFuncAttributeMaxDynamicSharedMemorySize,
                         (int)SHMEM_MAIN);
    return true;
}

extern "C" void kernel_launch(void* const* d_in, const int* in_sizes, int n_in,
                              void* d_out, int out_size)
{
    static bool ready = setup_once();
    (void)ready;

    const float* q = (const float*)d_in[0];
    const float* k = (const float*)d_in[1];
    const float* v = (const float*)d_in[2];
    float* out  = (float*)d_out;
    float* attn = out + OUT_ELEMS;

    const long long need = OUT_ELEMS + ATTN_ELEMS;
    const int write_attn = ((long long)out_size >= need) ? 1 : 0;

    dim3 grid(SS / QROWS, HH, BB);
    attn_sums<<<grid, 128, SHMEM_SUMS>>>(q, k);
    attn_main<<<grid, 128, SHMEM_MAIN>>>(q, k, v, out, attn, write_attn);
}